// round 16
// baseline (speedup 1.0000x reference)
#include <cuda_runtime.h>
#include <cuda_fp16.h>
#include <cstdint>

// WindowMultiHeadAttention  B=64 NW=64 L=49 E=384 H=12 hd=32
// R16: fused kernel = QKV + attention only (smem 64.4KB -> 3 CTAs/SM);
//      ctx written to global in C-frag layout; separate zero-smem out-proj
//      kernel reads ctx A-frags + frag-swizzled weights straight from L2.

#define LL   49
#define EE   384
#define HH   12
#define SCALE 0.17677669529663687f
#define NTHR 256

// ---- fused-kernel smem layout (b32 units) ----
#define OFF_X    0            // fp16 x:   49 x 196
#define OFF_QH   9604         // fp16 q:   2 x 49 x 20
#define OFF_KH   11564        // fp16 k:   2 x 56 x 20
#define OFF_VT   13804        // fp16 vT:  2 x 32 x 36
#define SMEM_U32 16108
#define SMEM_B   (SMEM_U32 * 4)   // 64432

// ---- statics ----
__device__ __align__(16) uint2  g_wqkv_f[6 * 24 * 24 * 32];   // [grp][blk][ks][lane]
__device__ __align__(16) uint2  g_wout_f[48 * 24 * 32];       // [blk][ks][lane]
__device__ __align__(16) float4 g_bm_f[64 * 12 * 4 * 7 * 32]; // [w][h][tm][nt][lane]
__device__ float g_bqkv_r[6 * 192];
__device__ __align__(16) uint2  g_ctx_f[(size_t)4096 * 4 * 48 * 32]; // [blk][tm][cb][lane]

__device__ __forceinline__ uint32_t smem_u32(const void* p) {
    uint32_t a;
    asm("{ .reg .u64 t; cvta.to.shared.u64 t, %1; cvt.u32.u64 %0, t; }" : "=r"(a) : "l"(p));
    return a;
}
__device__ __forceinline__ void sts_h(uint32_t addr, float f) {
    __half h = __float2half_rn(f);
    unsigned short u = *(unsigned short*)&h;
    asm volatile("st.shared.b16 [%0], %1;" :: "r"(addr), "h"(u) : "memory");
}
__device__ __forceinline__ uint32_t packh2(float a, float b) {
    __half2 h = __float22half2_rn(make_float2(a, b));
    return *(uint32_t*)&h;
}
#define LDSM_X4(r0,r1,r2,r3,a) \
    asm volatile("ldmatrix.sync.aligned.m8n8.x4.shared.b16 {%0,%1,%2,%3}, [%4];" \
        : "=r"(r0), "=r"(r1), "=r"(r2), "=r"(r3) : "r"(a))
#define LDSM_X2(r0,r1,a) \
    asm volatile("ldmatrix.sync.aligned.m8n8.x2.shared.b16 {%0,%1}, [%2];" \
        : "=r"(r0), "=r"(r1) : "r"(a))

__device__ __forceinline__ void mma_f16(float& c0, float& c1, float& c2, float& c3,
                                        uint32_t a0, uint32_t a1, uint32_t a2, uint32_t a3,
                                        uint32_t b0, uint32_t b1) {
    asm volatile("mma.sync.aligned.m16n8k16.row.col.f32.f16.f16.f32 "
        "{%0,%1,%2,%3}, {%4,%5,%6,%7}, {%8,%9}, {%0,%1,%2,%3};"
        : "+f"(c0), "+f"(c1), "+f"(c2), "+f"(c3)
        : "r"(a0), "r"(a1), "r"(a2), "r"(a3), "r"(b0), "r"(b1));
}

// ---------- prep ----------
__global__ void k_prep(const float* __restrict__ wqkv, const float* __restrict__ bqkv,
                       const float* __restrict__ wout,
                       const float* __restrict__ table, const int* __restrict__ rel,
                       const float* __restrict__ mask)
{
    const int idx = blockIdx.x * 256 + threadIdx.x;

    if (idx < 110592) {   // g_wqkv_f
        const int lane = idx & 31;
        int r = idx >> 5;
        const int ks = r % 24; r /= 24;
        const int blkq = r % 24;
        const int grp = r / 24;
        const int gg = lane >> 2, tt = lane & 3;
        const int col = blkq * 8 + gg;
        const int e = col / 96, rr = col - e * 96, part = rr >> 5, d = rr & 31;
        const int h = grp * 2 + e;
        const float s = (part == 0) ? SCALE : 1.0f;
        const int colw = part * 384 + h * 32 + d;
        const int k0 = ks * 16 + 2 * tt;
        uint2 v;
        v.x = packh2(wqkv[(size_t)k0 * 1152 + colw] * s,
                     wqkv[(size_t)(k0 + 1) * 1152 + colw] * s);
        v.y = packh2(wqkv[(size_t)(k0 + 8) * 1152 + colw] * s,
                     wqkv[(size_t)(k0 + 9) * 1152 + colw] * s);
        g_wqkv_f[idx] = v;
    }
    if (idx < 36864) {    // g_wout_f
        const int lane = idx & 31;
        int r = idx >> 5;
        const int ks = r % 24;
        const int blkq = r / 24;
        const int gg = lane >> 2, tt = lane & 3;
        const int col = blkq * 8 + gg;
        const int k0 = ks * 16 + 2 * tt;
        uint2 v;
        v.x = packh2(wout[(size_t)k0 * 384 + col], wout[(size_t)(k0 + 1) * 384 + col]);
        v.y = packh2(wout[(size_t)(k0 + 8) * 384 + col], wout[(size_t)(k0 + 9) * 384 + col]);
        g_wout_f[idx] = v;
    }
    if (idx < 688128) {   // g_bm_f (C-frag order, -1e30 on j pads)
        const int lane = idx & 31;
        int r = idx >> 5;
        const int nt = r % 7;  r /= 7;
        const int tm = r % 4;  r /= 4;
        const int h  = r % 12;
        const int w  = r / 12;
        const int gg = lane >> 2, tt = lane & 3;
        const int i0 = min(tm * 16 + gg, 48);
        const int i1 = min(tm * 16 + gg + 8, 48);
        const int j0 = nt * 8 + 2 * tt;
        const int j1 = j0 + 1;
        float4 v;
        v.x = (j0 < LL) ? table[rel[i0 * LL + j0] * HH + h] + mask[(size_t)w * (LL*LL) + i0 * LL + j0] : -1e30f;
        v.y = (j1 < LL) ? table[rel[i0 * LL + j1] * HH + h] + mask[(size_t)w * (LL*LL) + i0 * LL + j1] : -1e30f;
        v.z = (j0 < LL) ? table[rel[i1 * LL + j0] * HH + h] + mask[(size_t)w * (LL*LL) + i1 * LL + j0] : -1e30f;
        v.w = (j1 < LL) ? table[rel[i1 * LL + j1] * HH + h] + mask[(size_t)w * (LL*LL) + i1 * LL + j1] : -1e30f;
        g_bm_f[idx] = v;
    }
    if (idx < 1152) {
        const int grp = idx / 192, c = idx - grp * 192;
        const int e = c / 96, rr = c - e * 96, part = rr >> 5, d = rr & 31;
        const int h = grp * 2 + e;
        const float s = (part == 0) ? SCALE : 1.0f;
        g_bqkv_r[idx] = bqkv[part * 384 + h * 32 + d] * s;
    }
}

// ---------- fused: QKV + attention ----------
extern __shared__ float smem[];

__global__ __launch_bounds__(NTHR, 3)
void k_fused(const float* __restrict__ x)
{
    const int blk  = blockIdx.x;
    const int tid  = threadIdx.x;
    const int wid  = tid >> 5;        // 0..7
    const int lane = tid & 31;
    const int g    = lane >> 2;
    const int t    = lane & 3;
    const int wm   = wid >> 2;        // 0..1
    const int wn   = wid & 3;         // 0..3
    const int l7   = lane & 7;
    const int lb8  = (lane >> 3) & 1;
    const int lhi  = lane >> 4;

    const uint32_t sb = smem_u32(smem);
    const uint32_t xB  = sb + OFF_X * 4;
    const uint32_t qhB = sb + OFF_QH * 4;
    const uint32_t khB = sb + OFF_KH * 4;
    const uint32_t vtB = sb + OFF_VT * 4;

    const uint32_t aOff0 = (uint32_t)(min(wm * 32 + l7 + lb8 * 8, 48) * 784 + lhi * 16);
    const uint32_t aOff1 = (uint32_t)(min(wm * 32 + 16 + l7 + lb8 * 8, 48) * 784 + lhi * 16);

    // ---- load x (fp32 -> fp16 A-layout), zero vT + KH pad rows ----
    {
        const float* xg = x + (size_t)blk * (LL * EE);
        for (int u = tid; u < 49 * 48; u += NTHR) {
            const int row = u / 48, j = u - row * 48;
            const float4 v0 = *(const float4*)(xg + row * EE + j * 8);
            const float4 v1 = *(const float4*)(xg + row * EE + j * 8 + 4);
            const uint32_t p0 = packh2(v0.x, v0.y);
            const uint32_t p1 = packh2(v0.z, v0.w);
            const uint32_t p2 = packh2(v1.x, v1.y);
            const uint32_t p3 = packh2(v1.z, v1.w);
            asm volatile("st.shared.v4.b32 [%0], {%1,%2,%3,%4};" ::
                "r"(xB + (uint32_t)((row * 196 + j * 4) * 4)),
                "r"(p0), "r"(p1), "r"(p2), "r"(p3) : "memory");
        }
        for (int u = tid; u < 2304; u += NTHR)
            smem[OFF_VT + u] = 0.f;
        for (int u = tid; u < 280; u += NTHR) {
            const int e = u / 140, r2 = u - e * 140;
            smem[OFF_KH + e * 1120 + 49 * 20 + r2] = 0.f;
        }
    }
    __syncthreads();

    // ================= 6 groups of 2 heads =================
    for (int grp = 0; grp < 6; ++grp) {
        const int h0 = grp * 2;

        // ---- QKV GEMM: 2 N-passes of 24 cols (acc 24 regs), barrier-free ----
        float qacc[2][2][3][4];   // [np][mt][nt][4]
        #pragma unroll
        for (int np = 0; np < 2; ++np) {
            #pragma unroll
            for (int a = 0; a < 2; ++a)
                #pragma unroll
                for (int b = 0; b < 3; ++b)
                    #pragma unroll
                    for (int q = 0; q < 4; ++q) qacc[np][a][b][q] = 0.f;
        }
        {
            const uint32_t a0B = xB + aOff0;
            const uint32_t a1B = xB + aOff1;
            #pragma unroll
            for (int np = 0; np < 2; ++np) {
                const uint2* __restrict__ bgrp =
                    g_wqkv_f + (size_t)(grp * 24 + wn * 6 + np * 3) * 24 * 32;
                #pragma unroll 4
                for (int ks = 0; ks < 24; ++ks) {
                    uint32_t af[2][4];
                    LDSM_X4(af[0][0], af[0][1], af[0][2], af[0][3], a0B + ks * 32);
                    LDSM_X4(af[1][0], af[1][1], af[1][2], af[1][3], a1B + ks * 32);
                    #pragma unroll
                    for (int nt = 0; nt < 3; ++nt) {
                        const uint2 bb = bgrp[(nt * 24 + ks) * 32 + lane];
                        #pragma unroll
                        for (int mt = 0; mt < 2; ++mt)
                            mma_f16(qacc[np][mt][nt][0], qacc[np][mt][nt][1],
                                    qacc[np][mt][nt][2], qacc[np][mt][nt][3],
                                    af[mt][0], af[mt][1], af[mt][2], af[mt][3], bb.x, bb.y);
                    }
                }
            }
        }
        __syncthreads();   // prev-group attention readers done before epilogue STS

        // ---- epilogue: q,k,vT ----
        #pragma unroll
        for (int np = 0; np < 2; ++np) {
            #pragma unroll
            for (int mt = 0; mt < 2; ++mt) {
                const int r0 = wm * 32 + mt * 16 + g;
                const int r1 = r0 + 8;
                #pragma unroll
                for (int nt = 0; nt < 3; ++nt) {
                    const int col0 = wn * 48 + np * 24 + nt * 8 + 2 * t;
                    const float bb0 = g_bqkv_r[grp * 192 + col0];
                    const float bb1 = g_bqkv_r[grp * 192 + col0 + 1];
                    const int e = col0 / 96;
                    const int rr = col0 - e * 96;
                    const int part = rr >> 5;
                    const int d = rr & 31;
                    #pragma unroll
                    for (int hv = 0; hv < 2; ++hv) {
                        const int r = hv ? r1 : r0;
                        if (r >= LL) continue;
                        const float v0 = qacc[np][mt][nt][hv * 2 + 0] + bb0;
                        const float v1 = qacc[np][mt][nt][hv * 2 + 1] + bb1;
                        if (part == 0) {
                            asm volatile("st.shared.b32 [%0], %1;" ::
                                "r"(qhB + (uint32_t)(e * 3920 + r * 80 + d * 2)),
                                "r"(packh2(v0, v1)) : "memory");
                        } else if (part == 1) {
                            asm volatile("st.shared.b32 [%0], %1;" ::
                                "r"(khB + (uint32_t)(e * 4480 + r * 80 + d * 2)),
                                "r"(packh2(v0, v1)) : "memory");
                        } else {
                            const uint32_t a0 = vtB + (uint32_t)(e * 4608 + d * 144 + r * 2);
                            sts_h(a0, v0); sts_h(a0 + 144, v1);
                        }
                    }
                }
            }
        }
        __syncthreads();   // q/k/vT visible

        // ---- attention fully in-register on all 8 warps ----
        {
            const int e  = wid >> 2;
            const int tm = wid & 3;

            float sc[7][4];
            {
                const float4* __restrict__ bmf = g_bm_f +
                    ((((size_t)(blk & 63) * HH + (h0 + e)) * 4 + tm) * 7) * 32 + lane;
                #pragma unroll
                for (int nt = 0; nt < 7; ++nt) {
                    const float4 b = bmf[nt * 32];
                    sc[nt][0] = b.x; sc[nt][1] = b.y; sc[nt][2] = b.z; sc[nt][3] = b.w;
                }
            }
            {
                const uint32_t qB = qhB + (uint32_t)(e * 3920 +
                    min(tm * 16 + l7 + lb8 * 8, 48) * 80 + lhi * 16);
                const uint32_t kBase = khB + (uint32_t)(e * 4480 + l7 * 80 + lb8 * 16);
                #pragma unroll
                for (int ks = 0; ks < 2; ++ks) {
                    uint32_t a0, a1, a2, a3;
                    LDSM_X4(a0, a1, a2, a3, qB + ks * 32);
                    #pragma unroll
                    for (int nt = 0; nt < 7; ++nt) {
                        uint32_t b0, b1;
                        LDSM_X2(b0, b1, kBase + nt * 640 + ks * 32);
                        mma_f16(sc[nt][0], sc[nt][1], sc[nt][2], sc[nt][3], a0, a1, a2, a3, b0, b1);
                    }
                }
            }

            float m0 = -1e30f, m1 = -1e30f;
            #pragma unroll
            for (int nt = 0; nt < 7; ++nt) {
                m0 = fmaxf(m0, fmaxf(sc[nt][0], sc[nt][1]));
                m1 = fmaxf(m1, fmaxf(sc[nt][2], sc[nt][3]));
            }
            #pragma unroll
            for (int o = 1; o <= 2; o <<= 1) {
                m0 = fmaxf(m0, __shfl_xor_sync(0xffffffffu, m0, o));
                m1 = fmaxf(m1, __shfl_xor_sync(0xffffffffu, m1, o));
            }
            float s0 = 0.f, s1 = 0.f;
            #pragma unroll
            for (int nt = 0; nt < 7; ++nt) {
                sc[nt][0] = __expf(sc[nt][0] - m0);
                sc[nt][1] = __expf(sc[nt][1] - m0);
                sc[nt][2] = __expf(sc[nt][2] - m1);
                sc[nt][3] = __expf(sc[nt][3] - m1);
                s0 += sc[nt][0] + sc[nt][1];
                s1 += sc[nt][2] + sc[nt][3];
            }
            #pragma unroll
            for (int o = 1; o <= 2; o <<= 1) {
                s0 += __shfl_xor_sync(0xffffffffu, s0, o);
                s1 += __shfl_xor_sync(0xffffffffu, s1, o);
            }
            const float inv0 = 1.f / s0;
            const float inv1 = 1.f / s1;

            uint32_t aa[4][4];
            #pragma unroll
            for (int kb = 0; kb < 4; ++kb) {
                aa[kb][0] = packh2(sc[2*kb][0] * inv0, sc[2*kb][1] * inv0);
                aa[kb][1] = packh2(sc[2*kb][2] * inv1, sc[2*kb][3] * inv1);
                if (kb < 3) {
                    aa[kb][2] = packh2(sc[2*kb+1][0] * inv0, sc[2*kb+1][1] * inv0);
                    aa[kb][3] = packh2(sc[2*kb+1][2] * inv1, sc[2*kb+1][3] * inv1);
                } else {
                    aa[kb][2] = 0u; aa[kb][3] = 0u;
                }
            }
            float av[4][4];
            #pragma unroll
            for (int a = 0; a < 4; ++a)
                #pragma unroll
                for (int b = 0; b < 4; ++b) av[a][b] = 0.f;
            {
                const uint32_t vBase = vtB + (uint32_t)(e * 4608 + l7 * 144 + lb8 * 16);
                #pragma unroll
                for (int kb = 0; kb < 4; ++kb) {
                    #pragma unroll
                    for (int ntd = 0; ntd < 4; ++ntd) {
                        uint32_t b0, b1;
                        LDSM_X2(b0, b1, vBase + ntd * 1152 + kb * 32);
                        mma_f16(av[ntd][0], av[ntd][1], av[ntd][2], av[ntd][3],
                                aa[kb][0], aa[kb][1], aa[kb][2], aa[kb][3], b0, b1);
                    }
                }
            }
            // ctx C-frags -> GLOBAL (A-frag layout for out-proj); rows>=49 are
            // finite garbage discarded by the reader's store guard.
            #pragma unroll
            for (int ntd = 0; ntd < 4; ++ntd) {
                uint2 cv;
                cv.x = packh2(av[ntd][0], av[ntd][1]);
                cv.y = packh2(av[ntd][2], av[ntd][3]);
                g_ctx_f[(((size_t)blk * 4 + tm) * 48 + (h0 + e) * 4 + ntd) * 32 + lane] = cv;
            }
        }
    }
}

// ---------- out-proj: zero-smem, barrier-free ----------
__global__ __launch_bounds__(NTHR)
void k_outproj(const float* __restrict__ b_out, float* __restrict__ out)
{
    const int blk  = blockIdx.x;
    const int tid  = threadIdx.x;
    const int wid  = tid >> 5;
    const int lane = tid & 31;
    const int g    = lane >> 2;
    const int t    = lane & 3;
    const int wm   = wid >> 2;        // 0..1
    const int wn   = wid & 3;         // 0..3

    float* outp = out + (size_t)blk * (LL * EE);

    #pragma unroll
    for (int ph = 0; ph < 2; ++ph) {
        const uint2* __restrict__ bo = g_wout_f + (size_t)((wn * 2 + ph) * 6) * 24 * 32;
        float acc[2][6][4];
        #pragma unroll
        for (int a = 0; a < 2; ++a)
            #pragma unroll
            for (int b = 0; b < 6; ++b)
                #pragma unroll
                for (int q = 0; q < 4; ++q) acc[a][b][q] = 0.f;

        #pragma unroll 4
        for (int ks = 0; ks < 24; ++ks) {
            uint32_t af[2][4];
            #pragma unroll
            for (int mt = 0; mt < 2; ++mt) {
                const size_t base = (((size_t)blk * 4 + wm * 2 + mt) * 48 + 2 * ks) * 32 + lane;
                const uint2 u0 = g_ctx_f[base];
                const uint2 u1 = g_ctx_f[base + 32];
                af[mt][0] = u0.x; af[mt][1] = u0.y;
                af[mt][2] = u1.x; af[mt][3] = u1.y;
            }
            #pragma unroll
            for (int nt = 0; nt < 6; ++nt) {
                const uint2 bb = bo[(nt * 24 + ks) * 32 + lane];
                #pragma unroll
                for (int mt = 0; mt < 2; ++mt)
                    mma_f16(acc[mt][nt][0], acc[mt][nt][1], acc[mt][nt][2], acc[mt][nt][3],
                            af[mt][0], af[mt][1], af[mt][2], af[mt][3], bb.x, bb.y);
            }
        }

        #pragma unroll
        for (int mt = 0; mt < 2; ++mt) {
            const int r0 = wm * 32 + mt * 16 + g;
            const int r1 = r0 + 8;
            #pragma unroll
            for (int nt = 0; nt < 6; ++nt) {
                const int col = (wn * 2 + ph) * 48 + nt * 8 + 2 * t;
                const float b0 = b_out[col], b1 = b_out[col + 1];
                if (r0 < LL) {
                    float2 o; o.x = acc[mt][nt][0] + b0; o.y = acc[mt][nt][1] + b1;
                    *(float2*)(outp + r0 * EE + col) = o;
                }
                if (r1 < LL) {
                    float2 o; o.x = acc[mt][nt][2] + b0; o.y = acc[mt][nt][3] + b1;
                    *(float2*)(outp + r1 * EE + col) = o;
                }
            }
        }
    }
}

// ---------- launch ----------
extern "C" void kernel_launch(void* const* d_in, const int* in_sizes, int n_in,
                              void* d_out, int out_size)
{
    const float* x    = (const float*)d_in[0];
    const float* mask = (const float*)d_in[1];
    const float* wqkv = (const float*)d_in[2];
    const float* bqkv = (const float*)d_in[3];
    const float* wout = (const float*)d_in[4];
    const float* bout = (const float*)d_in[5];
    const float* bt   = (const float*)d_in[6];
    const int*   rel  = (const int*)d_in[7];
    float* out = (float*)d_out;

    cudaFuncSetAttribute(k_fused, cudaFuncAttributeMaxDynamicSharedMemorySize, SMEM_B);

    k_prep<<<(688128 + 255) / 256, 256>>>(wqkv, bqkv, wout, bt, rel, mask);
    k_fused<<<4096, NTHR, SMEM_B>>>(x);
    k_outproj<<<4096, NTHR>>>(bout, out);
}

// round 17
// speedup vs baseline: 1.2921x; 1.2921x over previous
#include <cuda_runtime.h>
#include <cuda_fp16.h>
#include <cstdint>

// WindowMultiHeadAttention  B=64 NW=64 L=49 E=384 H=12 hd=32
// R17 = R15 structure (fully fused, 256thr, 2 CTAs/SM) with QKV done as two
// SEQUENTIAL 24-col N-passes: acc footprint 48->24 regs so ptxas can
// software-pipeline the B loads inside the 128-reg cap. No spills.

#define LL   49
#define EE   384
#define HH   12
#define SCALE 0.17677669529663687f
#define NTHR 256

// ---- smem layout (b32 units) ----
#define OFF_X    0            // fp16 x:   49 x 196
#define OFF_CTX  9604         // fp16 ctx: 49 x 196
#define OFF_QH   19208        // fp16 q:   2 x 49 x 20
#define OFF_KH   21168        // fp16 k:   2 x 56 x 20
#define OFF_VT   23408        // fp16 vT:  2 x 32 x 36
#define SMEM_U32 25712
#define SMEM_B   (SMEM_U32 * 4)   // 102848

// ---- statics (frag-swizzled) ----
__device__ __align__(16) uint2  g_wqkv_f[6 * 24 * 24 * 32];   // [grp][blk][ks][lane]
__device__ __align__(16) uint2  g_wout_f[48 * 24 * 32];       // [blk][ks][lane]
__device__ __align__(16) float4 g_bm_f[64 * 12 * 4 * 7 * 32]; // [w][h][tm][nt][lane]
__device__ float g_bqkv_r[6 * 192];

__device__ __forceinline__ uint32_t smem_u32(const void* p) {
    uint32_t a;
    asm("{ .reg .u64 t; cvta.to.shared.u64 t, %1; cvt.u32.u64 %0, t; }" : "=r"(a) : "l"(p));
    return a;
}
__device__ __forceinline__ void sts_h(uint32_t addr, float f) {
    __half h = __float2half_rn(f);
    unsigned short u = *(unsigned short*)&h;
    asm volatile("st.shared.b16 [%0], %1;" :: "r"(addr), "h"(u) : "memory");
}
__device__ __forceinline__ uint32_t packh2(float a, float b) {
    __half2 h = __float22half2_rn(make_float2(a, b));
    return *(uint32_t*)&h;
}
#define LDSM_X4(r0,r1,r2,r3,a) \
    asm volatile("ldmatrix.sync.aligned.m8n8.x4.shared.b16 {%0,%1,%2,%3}, [%4];" \
        : "=r"(r0), "=r"(r1), "=r"(r2), "=r"(r3) : "r"(a))
#define LDSM_X2(r0,r1,a) \
    asm volatile("ldmatrix.sync.aligned.m8n8.x2.shared.b16 {%0,%1}, [%2];" \
        : "=r"(r0), "=r"(r1) : "r"(a))

__device__ __forceinline__ void mma_f16(float& c0, float& c1, float& c2, float& c3,
                                        uint32_t a0, uint32_t a1, uint32_t a2, uint32_t a3,
                                        uint32_t b0, uint32_t b1) {
    asm volatile("mma.sync.aligned.m16n8k16.row.col.f32.f16.f16.f32 "
        "{%0,%1,%2,%3}, {%4,%5,%6,%7}, {%8,%9}, {%0,%1,%2,%3};"
        : "+f"(c0), "+f"(c1), "+f"(c2), "+f"(c3)
        : "r"(a0), "r"(a1), "r"(a2), "r"(a3), "r"(b0), "r"(b1));
}

// ---------- prep ----------
__global__ void k_prep(const float* __restrict__ wqkv, const float* __restrict__ bqkv,
                       const float* __restrict__ wout,
                       const float* __restrict__ table, const int* __restrict__ rel,
                       const float* __restrict__ mask)
{
    const int idx = blockIdx.x * 256 + threadIdx.x;

    if (idx < 110592) {   // g_wqkv_f
        const int lane = idx & 31;
        int r = idx >> 5;
        const int ks = r % 24; r /= 24;
        const int blkq = r % 24;
        const int grp = r / 24;
        const int gg = lane >> 2, tt = lane & 3;
        const int col = blkq * 8 + gg;
        const int e = col / 96, rr = col - e * 96, part = rr >> 5, d = rr & 31;
        const int h = grp * 2 + e;
        const float s = (part == 0) ? SCALE : 1.0f;
        const int colw = part * 384 + h * 32 + d;
        const int k0 = ks * 16 + 2 * tt;
        uint2 v;
        v.x = packh2(wqkv[(size_t)k0 * 1152 + colw] * s,
                     wqkv[(size_t)(k0 + 1) * 1152 + colw] * s);
        v.y = packh2(wqkv[(size_t)(k0 + 8) * 1152 + colw] * s,
                     wqkv[(size_t)(k0 + 9) * 1152 + colw] * s);
        g_wqkv_f[idx] = v;
    }
    if (idx < 36864) {    // g_wout_f
        const int lane = idx & 31;
        int r = idx >> 5;
        const int ks = r % 24;
        const int blkq = r / 24;
        const int gg = lane >> 2, tt = lane & 3;
        const int col = blkq * 8 + gg;
        const int k0 = ks * 16 + 2 * tt;
        uint2 v;
        v.x = packh2(wout[(size_t)k0 * 384 + col], wout[(size_t)(k0 + 1) * 384 + col]);
        v.y = packh2(wout[(size_t)(k0 + 8) * 384 + col], wout[(size_t)(k0 + 9) * 384 + col]);
        g_wout_f[idx] = v;
    }
    if (idx < 688128) {   // g_bm_f (C-frag order, -1e30 on j pads)
        const int lane = idx & 31;
        int r = idx >> 5;
        const int nt = r % 7;  r /= 7;
        const int tm = r % 4;  r /= 4;
        const int h  = r % 12;
        const int w  = r / 12;
        const int gg = lane >> 2, tt = lane & 3;
        const int i0 = min(tm * 16 + gg, 48);
        const int i1 = min(tm * 16 + gg + 8, 48);
        const int j0 = nt * 8 + 2 * tt;
        const int j1 = j0 + 1;
        float4 v;
        v.x = (j0 < LL) ? table[rel[i0 * LL + j0] * HH + h] + mask[(size_t)w * (LL*LL) + i0 * LL + j0] : -1e30f;
        v.y = (j1 < LL) ? table[rel[i0 * LL + j1] * HH + h] + mask[(size_t)w * (LL*LL) + i0 * LL + j1] : -1e30f;
        v.z = (j0 < LL) ? table[rel[i1 * LL + j0] * HH + h] + mask[(size_t)w * (LL*LL) + i1 * LL + j0] : -1e30f;
        v.w = (j1 < LL) ? table[rel[i1 * LL + j1] * HH + h] + mask[(size_t)w * (LL*LL) + i1 * LL + j1] : -1e30f;
        g_bm_f[idx] = v;
    }
    if (idx < 1152) {
        const int grp = idx / 192, c = idx - grp * 192;
        const int e = c / 96, rr = c - e * 96, part = rr >> 5, d = rr & 31;
        const int h = grp * 2 + e;
        const float s = (part == 0) ? SCALE : 1.0f;
        g_bqkv_r[idx] = bqkv[part * 384 + h * 32 + d] * s;
    }
}

// ---------- fused ----------
extern __shared__ float smem[];

// epilogue for one 24-col QKV pass: scatter q/k/vT fragments to smem
__device__ __forceinline__ void qkv_epilogue(
    const float acc[2][3][4], int grp, int np, int wm, int wn, int g, int t,
    uint32_t qhB, uint32_t khB, uint32_t vtB)
{
    #pragma unroll
    for (int mt = 0; mt < 2; ++mt) {
        const int r0 = wm * 32 + mt * 16 + g;
        const int r1 = r0 + 8;
        #pragma unroll
        for (int nt = 0; nt < 3; ++nt) {
            const int col0 = wn * 48 + np * 24 + nt * 8 + 2 * t;
            const float bb0 = g_bqkv_r[grp * 192 + col0];
            const float bb1 = g_bqkv_r[grp * 192 + col0 + 1];
            const int e = col0 / 96;
            const int rr = col0 - e * 96;
            const int part = rr >> 5;
            const int d = rr & 31;
            #pragma unroll
            for (int hv = 0; hv < 2; ++hv) {
                const int r = hv ? r1 : r0;
                if (r >= LL) continue;
                const float v0 = acc[mt][nt][hv * 2 + 0] + bb0;
                const float v1 = acc[mt][nt][hv * 2 + 1] + bb1;
                if (part == 0) {
                    asm volatile("st.shared.b32 [%0], %1;" ::
                        "r"(qhB + (uint32_t)(e * 3920 + r * 80 + d * 2)),
                        "r"(packh2(v0, v1)) : "memory");
                } else if (part == 1) {
                    asm volatile("st.shared.b32 [%0], %1;" ::
                        "r"(khB + (uint32_t)(e * 4480 + r * 80 + d * 2)),
                        "r"(packh2(v0, v1)) : "memory");
                } else {
                    const uint32_t a0 = vtB + (uint32_t)(e * 4608 + d * 144 + r * 2);
                    sts_h(a0, v0); sts_h(a0 + 144, v1);
                }
            }
        }
    }
}

__global__ __launch_bounds__(NTHR, 2)
void k_fused(const float* __restrict__ x, const float* __restrict__ b_out,
             float* __restrict__ out)
{
    const int blk  = blockIdx.x;
    const int tid  = threadIdx.x;
    const int wid  = tid >> 5;        // 0..7
    const int lane = tid & 31;
    const int g    = lane >> 2;
    const int t    = lane & 3;
    const int wm   = wid >> 2;        // 0..1
    const int wn   = wid & 3;         // 0..3
    const int l7   = lane & 7;
    const int lb8  = (lane >> 3) & 1;
    const int lhi  = lane >> 4;

    const uint32_t sb = smem_u32(smem);
    const uint32_t xB   = sb + OFF_X * 4;
    const uint32_t ctxB = sb + OFF_CTX * 4;
    const uint32_t qhB  = sb + OFF_QH * 4;
    const uint32_t khB  = sb + OFF_KH * 4;
    const uint32_t vtB  = sb + OFF_VT * 4;

    const uint32_t aOff0 = (uint32_t)(min(wm * 32 + l7 + lb8 * 8, 48) * 784 + lhi * 16);
    const uint32_t aOff1 = (uint32_t)(min(wm * 32 + 16 + l7 + lb8 * 8, 48) * 784 + lhi * 16);

    // ---- load x (fp32 -> fp16 A-layout), zero vT + KH pad rows ----
    {
        const float* xg = x + (size_t)blk * (LL * EE);
        for (int u = tid; u < 49 * 48; u += NTHR) {
            const int row = u / 48, j = u - row * 48;
            const float4 v0 = *(const float4*)(xg + row * EE + j * 8);
            const float4 v1 = *(const float4*)(xg + row * EE + j * 8 + 4);
            const uint32_t p0 = packh2(v0.x, v0.y);
            const uint32_t p1 = packh2(v0.z, v0.w);
            const uint32_t p2 = packh2(v1.x, v1.y);
            const uint32_t p3 = packh2(v1.z, v1.w);
            asm volatile("st.shared.v4.b32 [%0], {%1,%2,%3,%4};" ::
                "r"(xB + (uint32_t)((row * 196 + j * 4) * 4)),
                "r"(p0), "r"(p1), "r"(p2), "r"(p3) : "memory");
        }
        for (int u = tid; u < 2304; u += NTHR)
            smem[OFF_VT + u] = 0.f;
        for (int u = tid; u < 280; u += NTHR) {
            const int e = u / 140, r2 = u - e * 140;
            smem[OFF_KH + e * 1120 + 49 * 20 + r2] = 0.f;
        }
    }
    __syncthreads();

    // ================= 6 groups of 2 heads =================
    for (int grp = 0; grp < 6; ++grp) {
        const int h0 = grp * 2;
        const uint32_t a0B = xB + aOff0;
        const uint32_t a1B = xB + aOff1;

        // ---- QKV pass 0 (cols wn*48 .. +24): acc 24 regs ----
        float acc[2][3][4];
        #pragma unroll
        for (int a = 0; a < 2; ++a)
            #pragma unroll
            for (int b = 0; b < 3; ++b)
                #pragma unroll
                for (int q = 0; q < 4; ++q) acc[a][b][q] = 0.f;
        {
            const uint2* __restrict__ bgrp = g_wqkv_f + (size_t)(grp * 24 + wn * 6) * 24 * 32;
            #pragma unroll 4
            for (int ks = 0; ks < 24; ++ks) {
                uint32_t af[2][4];
                LDSM_X4(af[0][0], af[0][1], af[0][2], af[0][3], a0B + ks * 32);
                LDSM_X4(af[1][0], af[1][1], af[1][2], af[1][3], a1B + ks * 32);
                #pragma unroll
                for (int nt = 0; nt < 3; ++nt) {
                    const uint2 bb = bgrp[(nt * 24 + ks) * 32 + lane];
                    #pragma unroll
                    for (int mt = 0; mt < 2; ++mt)
                        mma_f16(acc[mt][nt][0], acc[mt][nt][1], acc[mt][nt][2], acc[mt][nt][3],
                                af[mt][0], af[mt][1], af[mt][2], af[mt][3], bb.x, bb.y);
                }
            }
        }
        __syncthreads();   // prev-group attention readers done before epilogue STS
        qkv_epilogue(acc, grp, 0, wm, wn, g, t, qhB, khB, vtB);

        // ---- QKV pass 1 (cols wn*48+24 .. +48) ----
        #pragma unroll
        for (int a = 0; a < 2; ++a)
            #pragma unroll
            for (int b = 0; b < 3; ++b)
                #pragma unroll
                for (int q = 0; q < 4; ++q) acc[a][b][q] = 0.f;
        {
            const uint2* __restrict__ bgrp = g_wqkv_f + (size_t)(grp * 24 + wn * 6 + 3) * 24 * 32;
            #pragma unroll 4
            for (int ks = 0; ks < 24; ++ks) {
                uint32_t af[2][4];
                LDSM_X4(af[0][0], af[0][1], af[0][2], af[0][3], a0B + ks * 32);
                LDSM_X4(af[1][0], af[1][1], af[1][2], af[1][3], a1B + ks * 32);
                #pragma unroll
                for (int nt = 0; nt < 3; ++nt) {
                    const uint2 bb = bgrp[(nt * 24 + ks) * 32 + lane];
                    #pragma unroll
                    for (int mt = 0; mt < 2; ++mt)
                        mma_f16(acc[mt][nt][0], acc[mt][nt][1], acc[mt][nt][2], acc[mt][nt][3],
                                af[mt][0], af[mt][1], af[mt][2], af[mt][3], bb.x, bb.y);
                }
            }
        }
        qkv_epilogue(acc, grp, 1, wm, wn, g, t, qhB, khB, vtB);
        __syncthreads();   // q/k/vT visible

        // ---- attention fully in-register on all 8 warps ----
        {
            const int e  = wid >> 2;
            const int tm = wid & 3;
            const int iw0 = tm * 16 + g;
            const int iw1 = iw0 + 8;

            float sc[7][4];
            {
                const float4* __restrict__ bmf = g_bm_f +
                    ((((size_t)(blk & 63) * HH + (h0 + e)) * 4 + tm) * 7) * 32 + lane;
                #pragma unroll
                for (int nt = 0; nt < 7; ++nt) {
                    const float4 b = bmf[nt * 32];
                    sc[nt][0] = b.x; sc[nt][1] = b.y; sc[nt][2] = b.z; sc[nt][3] = b.w;
                }
            }
            {
                const uint32_t qB = qhB + (uint32_t)(e * 3920 +
                    min(tm * 16 + l7 + lb8 * 8, 48) * 80 + lhi * 16);
                const uint32_t kBase = khB + (uint32_t)(e * 4480 + l7 * 80 + lb8 * 16);
                #pragma unroll
                for (int ks = 0; ks < 2; ++ks) {
                    uint32_t a0, a1, a2, a3;
                    LDSM_X4(a0, a1, a2, a3, qB + ks * 32);
                    #pragma unroll
                    for (int nt = 0; nt < 7; ++nt) {
                        uint32_t b0, b1;
                        LDSM_X2(b0, b1, kBase + nt * 640 + ks * 32);
                        mma_f16(sc[nt][0], sc[nt][1], sc[nt][2], sc[nt][3], a0, a1, a2, a3, b0, b1);
                    }
                }
            }

            float m0 = -1e30f, m1 = -1e30f;
            #pragma unroll
            for (int nt = 0; nt < 7; ++nt) {
                m0 = fmaxf(m0, fmaxf(sc[nt][0], sc[nt][1]));
                m1 = fmaxf(m1, fmaxf(sc[nt][2], sc[nt][3]));
            }
            #pragma unroll
            for (int o = 1; o <= 2; o <<= 1) {
                m0 = fmaxf(m0, __shfl_xor_sync(0xffffffffu, m0, o));
                m1 = fmaxf(m1, __shfl_xor_sync(0xffffffffu, m1, o));
            }
            float s0 = 0.f, s1 = 0.f;
            #pragma unroll
            for (int nt = 0; nt < 7; ++nt) {
                sc[nt][0] = __expf(sc[nt][0] - m0);
                sc[nt][1] = __expf(sc[nt][1] - m0);
                sc[nt][2] = __expf(sc[nt][2] - m1);
                sc[nt][3] = __expf(sc[nt][3] - m1);
                s0 += sc[nt][0] + sc[nt][1];
                s1 += sc[nt][2] + sc[nt][3];
            }
            #pragma unroll
            for (int o = 1; o <= 2; o <<= 1) {
                s0 += __shfl_xor_sync(0xffffffffu, s0, o);
                s1 += __shfl_xor_sync(0xffffffffu, s1, o);
            }
            const float inv0 = 1.f / s0;
            const float inv1 = 1.f / s1;

            uint32_t aa[4][4];
            #pragma unroll
            for (int kb = 0; kb < 4; ++kb) {
                aa[kb][0] = packh2(sc[2*kb][0] * inv0, sc[2*kb][1] * inv0);
                aa[kb][1] = packh2(sc[2*kb][2] * inv1, sc[2*kb][3] * inv1);
                if (kb < 3) {
                    aa[kb][2] = packh2(sc[2*kb+1][0] * inv0, sc[2*kb+1][1] * inv0);
                    aa[kb][3] = packh2(sc[2*kb+1][2] * inv1, sc[2*kb+1][3] * inv1);
                } else {
                    aa[kb][2] = 0u; aa[kb][3] = 0u;
                }
            }
            float av[4][4];
            #pragma unroll
            for (int a = 0; a < 4; ++a)
                #pragma unroll
                for (int b = 0; b < 4; ++b) av[a][b] = 0.f;
            {
                const uint32_t vBase = vtB + (uint32_t)(e * 4608 + l7 * 144 + lb8 * 16);
                #pragma unroll
                for (int kb = 0; kb < 4; ++kb) {
                    #pragma unroll
                    for (int ntd = 0; ntd < 4; ++ntd) {
                        uint32_t b0, b1;
                        LDSM_X2(b0, b1, vBase + ntd * 1152 + kb * 32);
                        mma_f16(av[ntd][0], av[ntd][1], av[ntd][2], av[ntd][3],
                                aa[kb][0], aa[kb][1], aa[kb][2], aa[kb][3], b0, b1);
                    }
                }
            }
            #pragma unroll
            for (int ntd = 0; ntd < 4; ++ntd) {
                const uint32_t cidx = (uint32_t)((h0 + e) * 16 + ntd * 4 + t);
                if (iw0 < LL)
                    asm volatile("st.shared.b32 [%0], %1;" ::
                        "r"(ctxB + (uint32_t)(iw0 * 196 + cidx) * 4),
                        "r"(packh2(av[ntd][0], av[ntd][1])) : "memory");
                if (iw1 < LL)
                    asm volatile("st.shared.b32 [%0], %1;" ::
                        "r"(ctxB + (uint32_t)(iw1 * 196 + cidx) * 4),
                        "r"(packh2(av[ntd][2], av[ntd][3])) : "memory");
            }
        }
    }
    __syncthreads();   // ctx complete

    // ====== out-proj: barrier-free, frag-swizzled B, LDSM A, two N-passes ======
    {
        float* outp = out + (size_t)blk * (LL * EE);
        const uint32_t a0B = ctxB + aOff0;
        const uint32_t a1B = ctxB + aOff1;

        #pragma unroll
        for (int ph = 0; ph < 2; ++ph) {
            const uint2* __restrict__ bo = g_wout_f + (size_t)((wn * 2 + ph) * 6) * 24 * 32;
            float acc[2][6][4];
            #pragma unroll
            for (int a = 0; a < 2; ++a)
                #pragma unroll
                for (int b = 0; b < 6; ++b)
                    #pragma unroll
                    for (int q = 0; q < 4; ++q) acc[a][b][q] = 0.f;

            #pragma unroll 4
            for (int ks = 0; ks < 24; ++ks) {
                uint32_t af[2][4];
                LDSM_X4(af[0][0], af[0][1], af[0][2], af[0][3], a0B + ks * 32);
                LDSM_X4(af[1][0], af[1][1], af[1][2], af[1][3], a1B + ks * 32);
                #pragma unroll
                for (int nt = 0; nt < 6; ++nt) {
                    const uint2 bb = bo[(nt * 24 + ks) * 32 + lane];
                    #pragma unroll
                    for (int mt = 0; mt < 2; ++mt)
                        mma_f16(acc[mt][nt][0], acc[mt][nt][1], acc[mt][nt][2], acc[mt][nt][3],
                                af[mt][0], af[mt][1], af[mt][2], af[mt][3], bb.x, bb.y);
                }
            }

            #pragma unroll
            for (int mt = 0; mt < 2; ++mt) {
                const int r0 = wm * 32 + mt * 16 + g;
                const int r1 = r0 + 8;
                #pragma unroll
                for (int nt = 0; nt < 6; ++nt) {
                    const int col = (wn * 2 + ph) * 48 + nt * 8 + 2 * t;
                    const float b0 = b_out[col], b1 = b_out[col + 1];
                    if (r0 < LL) {
                        float2 o; o.x = acc[mt][nt][0] + b0; o.y = acc[mt][nt][1] + b1;
                        *(float2*)(outp + r0 * EE + col) = o;
                    }
                    if (r1 < LL) {
                        float2 o; o.x = acc[mt][nt][2] + b0; o.y = acc[mt][nt][3] + b1;
                        *(float2*)(outp + r1 * EE + col) = o;
                    }
                }
            }
        }
    }
}

// ---------- launch ----------
extern "C" void kernel_launch(void* const* d_in, const int* in_sizes, int n_in,
                              void* d_out, int out_size)
{
    const float* x    = (const float*)d_in[0];
    const float* mask = (const float*)d_in[1];
    const float* wqkv = (const float*)d_in[2];
    const float* bqkv = (const float*)d_in[3];
    const float* wout = (const float*)d_in[4];
    const float* bout = (const float*)d_in[5];
    const float* bt   = (const float*)d_in[6];
    const int*   rel  = (const int*)d_in[7];
    float* out = (float*)d_out;

    cudaFuncSetAttribute(k_fused, cudaFuncAttributeMaxDynamicSharedMemorySize, SMEM_B);

    k_prep<<<(688128 + 255) / 256, 256>>>(wqkv, bqkv, wout, bt, rel, mask);
    k_fused<<<4096, NTHR, SMEM_B>>>(x, bout, out);
}